// round 1
// baseline (speedup 1.0000x reference)
#include <cuda_runtime.h>
#include <cstdint>

#define D 128
#define NMAX 100000
#define EMAX 1600000

// -------- scratch (static device allocations; no cudaMalloc allowed) --------
__device__ float g_xw[(size_t)NMAX * D];   // x @ W   (51.2 MB)
__device__ float g_dinv[NMAX];
__device__ int   g_deg[NMAX];
__device__ int   g_is64;

// ---------------------------------------------------------------------------
// dtype detection: edge_index may be int64 (as written) or int32 (jax x64 off).
// If int64 with values in [0, N), every odd 32-bit word is 0.
// ---------------------------------------------------------------------------
__global__ void detect_kernel(const int* ei32, int nsamp) {
    __shared__ int s_nonzero;
    if (threadIdx.x == 0) s_nonzero = 0;
    __syncthreads();
    int bad = 0;
    for (int i = threadIdx.x; i < nsamp; i += blockDim.x)
        if (ei32[2 * i + 1] != 0) bad = 1;
    if (bad) atomicOr(&s_nonzero, 1);
    __syncthreads();
    if (threadIdx.x == 0) g_is64 = s_nonzero ? 0 : 1;
}

__global__ void deg_init(int n) {
    int i = blockIdx.x * blockDim.x + threadIdx.x;
    if (i < n) g_deg[i] = 1;   // self loop
}

__global__ void deg_count(const void* ei, int E) {
    int e = blockIdx.x * blockDim.x + threadIdx.x;
    if (e >= E) return;
    int d;
    if (g_is64) d = (int)((const long long*)ei)[(size_t)E + e];
    else        d = ((const int*)ei)[(size_t)E + e];
    atomicAdd(&g_deg[d], 1);
}

__global__ void dinv_kernel(int n) {
    int i = blockIdx.x * blockDim.x + threadIdx.x;
    if (i < n) g_dinv[i] = rsqrtf((float)g_deg[i]);
}

// ---------------------------------------------------------------------------
// GEMM: C = x @ B, B = W (blockIdx.y==0 -> g_xw) or Wl (y==1 -> out).
// BM=64, BN=128 (full D_OUT), BK=32. 256 threads, thread tile 4x8,
// packed fma.rn.f32x2 along the N dimension.
// ---------------------------------------------------------------------------
#define BM 64
#define BN 128
#define BK 32

__device__ __forceinline__ unsigned long long pack2(float x, float y) {
    unsigned long long r;
    asm("mov.b64 %0, {%1, %2};" : "=l"(r) : "f"(x), "f"(y));
    return r;
}
__device__ __forceinline__ void unpack2(unsigned long long v, float& x, float& y) {
    asm("mov.b64 {%0, %1}, %2;" : "=f"(x), "=f"(y) : "l"(v));
}
__device__ __forceinline__ void fma2(unsigned long long& d,
                                     unsigned long long a, unsigned long long b) {
    asm("fma.rn.f32x2 %0, %1, %2, %0;" : "+l"(d) : "l"(a), "l"(b));
}

__global__ __launch_bounds__(256) void gemm_kernel(
    const float* __restrict__ x,
    const float* __restrict__ W,
    const float* __restrict__ Wl,
    float* __restrict__ outh, int M)
{
    __shared__ float As[BM][BK + 1];   // +1 pad: conflict-free transposeless store
    __shared__ float Bs[BK][BN];

    const float* B = (blockIdx.y == 0) ? W : Wl;
    float* Cout    = (blockIdx.y == 0) ? g_xw : outh;

    const int row0 = blockIdx.x * BM;
    const int tid  = threadIdx.x;
    const int tr   = tid >> 4;        // 0..15
    const int tc   = tid & 15;        // 0..15
    const int m0   = tr * 4;
    const int n0   = tc * 8;

    unsigned long long acc[4][4];
    #pragma unroll
    for (int m = 0; m < 4; m++)
        #pragma unroll
        for (int p = 0; p < 4; p++) acc[m][p] = 0ull;

    for (int k0 = 0; k0 < D; k0 += BK) {
        // load A tile 64x32 (2 float4 / thread)
        #pragma unroll
        for (int i = 0; i < 2; i++) {
            int idx = tid + i * 256;       // 0..511
            int r   = idx >> 3;
            int c4  = (idx & 7) * 4;
            float4 v = make_float4(0.f, 0.f, 0.f, 0.f);
            int grow = row0 + r;
            if (grow < M) v = *(const float4*)&x[(size_t)grow * D + k0 + c4];
            As[r][c4 + 0] = v.x; As[r][c4 + 1] = v.y;
            As[r][c4 + 2] = v.z; As[r][c4 + 3] = v.w;
        }
        // load B tile 32x128 (4 float4 / thread)
        #pragma unroll
        for (int i = 0; i < 4; i++) {
            int idx = tid + i * 256;       // 0..1023
            int r   = idx >> 5;
            int c4  = (idx & 31) * 4;
            float4 v = *(const float4*)&B[(size_t)(k0 + r) * D + c4];
            *(float4*)&Bs[r][c4] = v;
        }
        __syncthreads();

        #pragma unroll
        for (int kk = 0; kk < BK; kk++) {
            unsigned long long ap[4];
            #pragma unroll
            for (int m = 0; m < 4; m++) {
                float a = As[m0 + m][kk];
                ap[m] = pack2(a, a);
            }
            ulonglong2 bq0 = *(const ulonglong2*)&Bs[kk][n0];
            ulonglong2 bq1 = *(const ulonglong2*)&Bs[kk][n0 + 4];
            unsigned long long bp[4] = { bq0.x, bq0.y, bq1.x, bq1.y };
            #pragma unroll
            for (int m = 0; m < 4; m++)
                #pragma unroll
                for (int p = 0; p < 4; p++)
                    fma2(acc[m][p], ap[m], bp[p]);
        }
        __syncthreads();
    }

    #pragma unroll
    for (int m = 0; m < 4; m++) {
        int grow = row0 + m0 + m;
        if (grow >= M) continue;
        float o[8];
        #pragma unroll
        for (int p = 0; p < 4; p++) unpack2(acc[m][p], o[2 * p], o[2 * p + 1]);
        *(float4*)&Cout[(size_t)grow * D + n0]     = make_float4(o[0], o[1], o[2], o[3]);
        *(float4*)&Cout[(size_t)grow * D + n0 + 4] = make_float4(o[4], o[5], o[6], o[7]);
    }
}

// ---------------------------------------------------------------------------
// Edge scatter: one warp per edge. out[dst] += xw[src] * dinv[src]*dinv[dst]
// via red.global.add.v4.f32 (16B vector reduction, sm_90+).
// ---------------------------------------------------------------------------
__global__ __launch_bounds__(256) void scatter_kernel(
    const void* __restrict__ ei, float* __restrict__ out, int E)
{
    int gtid = blockIdx.x * blockDim.x + threadIdx.x;
    int e    = gtid >> 5;
    int lane = gtid & 31;
    if (e >= E) return;
    int s, d;
    if (g_is64) {
        const long long* p = (const long long*)ei;
        s = (int)p[e];
        d = (int)p[(size_t)E + e];
    } else {
        const int* p = (const int*)ei;
        s = p[e];
        d = p[(size_t)E + e];
    }
    float c = g_dinv[s] * g_dinv[d];
    float4 v = *(const float4*)&g_xw[(size_t)s * D + lane * 4];
    float* dstp = &out[(size_t)d * D + lane * 4];
    asm volatile("red.global.add.v4.f32 [%0], {%1, %2, %3, %4};"
                 :: "l"(dstp), "f"(v.x * c), "f"(v.y * c), "f"(v.z * c), "f"(v.w * c)
                 : "memory");
}

// ---------------------------------------------------------------------------
// LayerNorm (warp per row), fusing self-loop term + biases:
//   h = out + xw * dinv^2 + (b + bl);  out = (h-mu)*rstd*gamma + beta
// ---------------------------------------------------------------------------
__global__ __launch_bounds__(256) void ln_kernel(
    float* __restrict__ out,
    const float* __restrict__ b,  const float* __restrict__ bl,
    const float* __restrict__ gamma, const float* __restrict__ beta, int n)
{
    int gtid = blockIdx.x * blockDim.x + threadIdx.x;
    int r    = gtid >> 5;
    int lane = gtid & 31;
    if (r >= n) return;
    int j = lane * 4;
    float sd = g_dinv[r];
    sd = sd * sd;

    float4 h  = *(float4*)&out[(size_t)r * D + j];
    float4 xw = *(const float4*)&g_xw[(size_t)r * D + j];
    float4 b4 = *(const float4*)&b[j];
    float4 l4 = *(const float4*)&bl[j];
    h.x += xw.x * sd + b4.x + l4.x;
    h.y += xw.y * sd + b4.y + l4.y;
    h.z += xw.z * sd + b4.z + l4.z;
    h.w += xw.w * sd + b4.w + l4.w;

    float s = h.x + h.y + h.z + h.w;
    #pragma unroll
    for (int o = 16; o > 0; o >>= 1) s += __shfl_xor_sync(0xFFFFFFFFu, s, o);
    float mu = s * (1.f / 128.f);

    float dx = h.x - mu, dy = h.y - mu, dz = h.z - mu, dw = h.w - mu;
    float sq = dx * dx + dy * dy + dz * dz + dw * dw;
    #pragma unroll
    for (int o = 16; o > 0; o >>= 1) sq += __shfl_xor_sync(0xFFFFFFFFu, sq, o);
    float rstd = rsqrtf(sq * (1.f / 128.f) + 1e-5f);

    float4 g4 = *(const float4*)&gamma[j];
    float4 e4 = *(const float4*)&beta[j];
    float4 o4;
    o4.x = dx * rstd * g4.x + e4.x;
    o4.y = dy * rstd * g4.y + e4.y;
    o4.z = dz * rstd * g4.z + e4.z;
    o4.w = dw * rstd * g4.w + e4.w;
    *(float4*)&out[(size_t)r * D + j] = o4;
}

// ---------------------------------------------------------------------------
extern "C" void kernel_launch(void* const* d_in, const int* in_sizes, int n_in,
                              void* d_out, int out_size)
{
    const float* x     = (const float*)d_in[0];
    const void*  ei    = d_in[1];
    const float* W     = (const float*)d_in[2];
    const float* b     = (const float*)d_in[3];
    const float* Wl    = (const float*)d_in[4];
    const float* bl    = (const float*)d_in[5];
    const float* gamma = (const float*)d_in[6];
    const float* beta  = (const float*)d_in[7];
    float* out = (float*)d_out;

    int N = in_sizes[0] / D;
    int E = in_sizes[1] / 2;

    detect_kernel<<<1, 256>>>((const int*)ei, 512);
    deg_init<<<(N + 255) / 256, 256>>>(N);
    deg_count<<<(E + 255) / 256, 256>>>(ei, E);
    dinv_kernel<<<(N + 255) / 256, 256>>>(N);

    dim3 ggrid((N + BM - 1) / BM, 2);
    gemm_kernel<<<ggrid, 256>>>(x, W, Wl, out, N);

    long long sw = (long long)E * 32;
    scatter_kernel<<<(unsigned)((sw + 255) / 256), 256>>>(ei, out, E);

    long long lw = (long long)N * 32;
    ln_kernel<<<(unsigned)((lw + 255) / 256), 256>>>(out, b, bl, gamma, beta, N);
}

// round 4
// speedup vs baseline: 1.2515x; 1.2515x over previous
#include <cuda_runtime.h>
#include <cuda_bf16.h>
#include <cstdint>

#define D 128
#define NMAX 100000
#define EMAX 1600000

// -------- scratch (static device allocations; no cudaMalloc allowed) --------
__device__ float g_xw[(size_t)NMAX * D];   // x @ W   (51.2 MB)
__device__ float g_dinv[NMAX];
__device__ int   g_deg[NMAX];
__device__ int   g_is64;

// ---------------------------------------------------------------------------
// dtype detection: edge_index may be int64 or int32.
// ---------------------------------------------------------------------------
__global__ void detect_kernel(const int* ei32, int nsamp) {
    __shared__ int s_nonzero;
    if (threadIdx.x == 0) s_nonzero = 0;
    __syncthreads();
    int bad = 0;
    for (int i = threadIdx.x; i < nsamp; i += blockDim.x)
        if (ei32[2 * i + 1] != 0) bad = 1;
    if (bad) atomicOr(&s_nonzero, 1);
    __syncthreads();
    if (threadIdx.x == 0) g_is64 = s_nonzero ? 0 : 1;
}

__global__ void deg_init(int n) {
    int i = blockIdx.x * blockDim.x + threadIdx.x;
    if (i < n) g_deg[i] = 1;   // self loop
}

__global__ void deg_count(const void* ei, int E) {
    int e = blockIdx.x * blockDim.x + threadIdx.x;
    if (e >= E) return;
    int d;
    if (g_is64) d = (int)((const long long*)ei)[(size_t)E + e];
    else        d = ((const int*)ei)[(size_t)E + e];
    atomicAdd(&g_deg[d], 1);
}

__global__ void dinv_kernel(int n) {
    int i = blockIdx.x * blockDim.x + threadIdx.x;
    if (i < n) g_dinv[i] = rsqrtf((float)g_deg[i]);
}

// ===========================================================================
// GEMM via mma.sync.m16n8k16 bf16 (fp32 accum), hi/lo split for fp32 accuracy:
//   C = Ahi*Bhi + Ahi*Blo + Alo*Bhi
// Per CTA: 128(M) x 128(N) x 128(K). 256 threads = 8 warps (4 along M x 2
// along N). A in smem row-major [m][k], B transposed [n][k], stride 136 bf16
// (272 B, 16B-aligned, ldmatrix conflict-free).
// grid.y = 0 -> W -> g_xw,  grid.y = 1 -> Wl -> d_out.
// ===========================================================================

#define SSTR 136                       // bf16 elements per smem row
#define TILE_B (128 * SSTR * 2)        // 34816 bytes
#define OFF_AHI 0
#define OFF_ALO (TILE_B)
#define OFF_BHI (2 * TILE_B)
#define OFF_BLO (3 * TILE_B)
#define GEMM_SMEM (4 * TILE_B)         // 139264

__device__ __forceinline__ uint32_t smem_u32(const void* p) {
    uint32_t a;
    asm("{ .reg .u64 t; cvta.to.shared.u64 t, %1; cvt.u32.u64 %0, t; }"
        : "=r"(a) : "l"(p));
    return a;
}

__device__ __forceinline__ void ldsm_x4(uint32_t& r0, uint32_t& r1,
                                        uint32_t& r2, uint32_t& r3, uint32_t addr) {
    asm volatile("ldmatrix.sync.aligned.m8n8.x4.shared.b16 {%0,%1,%2,%3}, [%4];"
                 : "=r"(r0), "=r"(r1), "=r"(r2), "=r"(r3) : "r"(addr));
}

__device__ __forceinline__ void mma16816(float* c, const uint32_t* a,
                                         const uint32_t* b) {
    asm volatile(
        "mma.sync.aligned.m16n8k16.row.col.f32.bf16.bf16.f32 "
        "{%0,%1,%2,%3}, {%4,%5,%6,%7}, {%8,%9}, {%0,%1,%2,%3};"
        : "+f"(c[0]), "+f"(c[1]), "+f"(c[2]), "+f"(c[3])
        : "r"(a[0]), "r"(a[1]), "r"(a[2]), "r"(a[3]), "r"(b[0]), "r"(b[1]));
}

__global__ __launch_bounds__(256, 1) void gemm_mma_kernel(
    const float* __restrict__ x,
    const float* __restrict__ W,
    const float* __restrict__ Wl,
    float* __restrict__ outh, int M)
{
    extern __shared__ char smem[];
    const uint32_t sb = smem_u32(smem);
    const int tid  = threadIdx.x;
    const int wid  = tid >> 5;
    const int lane = tid & 31;
    const int row0 = blockIdx.x * 128;

    const float* B = (blockIdx.y == 0) ? W : Wl;
    float* Cout    = (blockIdx.y == 0) ? g_xw : outh;

    // ---- convert x tile: thread handles half a row (64 cols) ----
    {
        const int r  = tid >> 1;
        const int hf = tid & 1;
        const int grow = row0 + r;
        const bool ok = grow < M;
        const float* xr = x + (size_t)(ok ? grow : 0) * D + hf * 64;
        char* pHi = smem + OFF_AHI;
        char* pLo = smem + OFF_ALO;
        const uint32_t rb = (uint32_t)(r * SSTR + hf * 64) * 2;
        #pragma unroll
        for (int c4 = 0; c4 < 16; c4++) {
            float4 v = ok ? *(const float4*)&xr[c4 * 4]
                          : make_float4(0.f, 0.f, 0.f, 0.f);
            float f[4] = { v.x, v.y, v.z, v.w };
            __nv_bfloat16 h[4], l[4];
            #pragma unroll
            for (int j = 0; j < 4; j++) {
                h[j] = __float2bfloat16(f[j]);
                l[j] = __float2bfloat16(f[j] - __bfloat162float(h[j]));
            }
            *(__nv_bfloat162*)(pHi + rb + c4 * 8)     = __nv_bfloat162(h[0], h[1]);
            *(__nv_bfloat162*)(pHi + rb + c4 * 8 + 4) = __nv_bfloat162(h[2], h[3]);
            *(__nv_bfloat162*)(pLo + rb + c4 * 8)     = __nv_bfloat162(l[0], l[1]);
            *(__nv_bfloat162*)(pLo + rb + c4 * 8 + 4) = __nv_bfloat162(l[2], l[3]);
        }
    }

    // ---- convert weight tile transposed: Bs[n][k] = B[k][n] ----
    {
        const int n  = tid >> 1;
        const int kh = tid & 1;
        const float* bp = B + n + (size_t)kh * 64 * D;
        char* pHi = smem + OFF_BHI;
        char* pLo = smem + OFF_BLO;
        #pragma unroll 4
        for (int kk = 0; kk < 64; kk++) {
            float f = bp[(size_t)kk * D];
            __nv_bfloat16 h = __float2bfloat16(f);
            __nv_bfloat16 l = __float2bfloat16(f - __bfloat162float(h));
            uint32_t off = (uint32_t)(n * SSTR + kh * 64 + kk) * 2;
            *(__nv_bfloat16*)(pHi + off) = h;
            *(__nv_bfloat16*)(pLo + off) = l;
        }
    }
    __syncthreads();

    // ---- warp tiling: 4 warps along M (32 rows), 2 along N (64 cols) ----
    const int mi = wid & 3;
    const int ni = wid >> 2;

    float c[2][8][4];
    #pragma unroll
    for (int mt = 0; mt < 2; mt++)
        #pragma unroll
        for (int nt = 0; nt < 8; nt++)
            #pragma unroll
            for (int q = 0; q < 4; q++) c[mt][nt][q] = 0.f;

    const int lmat = lane >> 3;
    const int lr   = lane & 7;
    const int rowc = ((lmat & 1) << 3) + lr;   // row offset within 16-row tile
    const int colc = (lmat >> 1) << 3;         // col offset (k half)

    #pragma unroll
    for (int p = 0; p < 3; p++) {
        const uint32_t abase = sb + ((p < 2) ? OFF_AHI : OFF_ALO);
        const uint32_t bbase = sb + ((p == 1) ? OFF_BLO : OFF_BHI);
        const uint32_t a_rc = (uint32_t)((mi * 32 + rowc) * SSTR + colc) * 2;
        const uint32_t b_rc = (uint32_t)((ni * 64 + rowc) * SSTR + colc) * 2;

        #pragma unroll
        for (int k0 = 0; k0 < 8; k0++) {
            const uint32_t kb = (uint32_t)(k0 * 16) * 2;
            uint32_t afr[2][4];
            #pragma unroll
            for (int mt = 0; mt < 2; mt++)
                ldsm_x4(afr[mt][0], afr[mt][1], afr[mt][2], afr[mt][3],
                        abase + a_rc + kb + (uint32_t)(mt * 16 * SSTR) * 2);
            uint32_t bfr[8][2];
            #pragma unroll
            for (int nb = 0; nb < 4; nb++) {
                uint32_t r0, r1, r2, r3;
                ldsm_x4(r0, r1, r2, r3,
                        bbase + b_rc + kb + (uint32_t)(nb * 16 * SSTR) * 2);
                bfr[nb * 2][0]     = r0;  bfr[nb * 2][1]     = r2;
                bfr[nb * 2 + 1][0] = r1;  bfr[nb * 2 + 1][1] = r3;
            }
            #pragma unroll
            for (int mt = 0; mt < 2; mt++)
                #pragma unroll
                for (int nt = 0; nt < 8; nt++)
                    mma16816(c[mt][nt], afr[mt], bfr[nt]);
        }
    }

    // ---- epilogue: write fragments directly to global ----
    const int g   = lane >> 2;
    const int tig = lane & 3;
    #pragma unroll
    for (int mt = 0; mt < 2; mt++) {
        #pragma unroll
        for (int nt = 0; nt < 8; nt++) {
            const int col  = ni * 64 + nt * 8 + tig * 2;
            const int row  = row0 + mi * 32 + mt * 16 + g;
            if (row < M)
                *(float2*)&Cout[(size_t)row * D + col] =
                    make_float2(c[mt][nt][0], c[mt][nt][1]);
            if (row + 8 < M)
                *(float2*)&Cout[(size_t)(row + 8) * D + col] =
                    make_float2(c[mt][nt][2], c[mt][nt][3]);
        }
    }
}

// ---------------------------------------------------------------------------
// Edge scatter: one warp per edge. out[dst] += xw[src] * dinv[src]*dinv[dst]
// ---------------------------------------------------------------------------
__global__ __launch_bounds__(256) void scatter_kernel(
    const void* __restrict__ ei, float* __restrict__ out, int E)
{
    int gtid = blockIdx.x * blockDim.x + threadIdx.x;
    int e    = gtid >> 5;
    int lane = gtid & 31;
    if (e >= E) return;
    int s, d;
    if (g_is64) {
        const long long* p = (const long long*)ei;
        s = (int)p[e];
        d = (int)p[(size_t)E + e];
    } else {
        const int* p = (const int*)ei;
        s = p[e];
        d = p[(size_t)E + e];
    }
    float c = g_dinv[s] * g_dinv[d];
    float4 v = *(const float4*)&g_xw[(size_t)s * D + lane * 4];
    float* dstp = &out[(size_t)d * D + lane * 4];
    asm volatile("red.global.add.v4.f32 [%0], {%1, %2, %3, %4};"
                 :: "l"(dstp), "f"(v.x * c), "f"(v.y * c), "f"(v.z * c), "f"(v.w * c)
                 : "memory");
}

// ---------------------------------------------------------------------------
// LayerNorm (warp per row), fused self-loop term + biases.
// ---------------------------------------------------------------------------
__global__ __launch_bounds__(256) void ln_kernel(
    float* __restrict__ out,
    const float* __restrict__ b,  const float* __restrict__ bl,
    const float* __restrict__ gamma, const float* __restrict__ beta, int n)
{
    int gtid = blockIdx.x * blockDim.x + threadIdx.x;
    int r    = gtid >> 5;
    int lane = gtid & 31;
    if (r >= n) return;
    int j = lane * 4;
    float sd = g_dinv[r];
    sd = sd * sd;

    float4 h  = *(float4*)&out[(size_t)r * D + j];
    float4 xw = *(const float4*)&g_xw[(size_t)r * D + j];
    float4 b4 = *(const float4*)&b[j];
    float4 l4 = *(const float4*)&bl[j];
    h.x += xw.x * sd + b4.x + l4.x;
    h.y += xw.y * sd + b4.y + l4.y;
    h.z += xw.z * sd + b4.z + l4.z;
    h.w += xw.w * sd + b4.w + l4.w;

    float s = h.x + h.y + h.z + h.w;
    #pragma unroll
    for (int o = 16; o > 0; o >>= 1) s += __shfl_xor_sync(0xFFFFFFFFu, s, o);
    float mu = s * (1.f / 128.f);

    float dx = h.x - mu, dy = h.y - mu, dz = h.z - mu, dw = h.w - mu;
    float sq = dx * dx + dy * dy + dz * dz + dw * dw;
    #pragma unroll
    for (int o = 16; o > 0; o >>= 1) sq += __shfl_xor_sync(0xFFFFFFFFu, sq, o);
    float rstd = rsqrtf(sq * (1.f / 128.f) + 1e-5f);

    float4 g4 = *(const float4*)&gamma[j];
    float4 e4 = *(const float4*)&beta[j];
    float4 o4;
    o4.x = dx * rstd * g4.x + e4.x;
    o4.y = dy * rstd * g4.y + e4.y;
    o4.z = dz * rstd * g4.z + e4.z;
    o4.w = dw * rstd * g4.w + e4.w;
    *(float4*)&out[(size_t)r * D + j] = o4;
}

// ---------------------------------------------------------------------------
extern "C" void kernel_launch(void* const* d_in, const int* in_sizes, int n_in,
                              void* d_out, int out_size)
{
    const float* x     = (const float*)d_in[0];
    const void*  ei    = d_in[1];
    const float* W     = (const float*)d_in[2];
    const float* b     = (const float*)d_in[3];
    const float* Wl    = (const float*)d_in[4];
    const float* bl    = (const float*)d_in[5];
    const float* gamma = (const float*)d_in[6];
    const float* beta  = (const float*)d_in[7];
    float* out = (float*)d_out;

    int N = in_sizes[0] / D;
    int E = in_sizes[1] / 2;

    cudaFuncSetAttribute(gemm_mma_kernel,
                         cudaFuncAttributeMaxDynamicSharedMemorySize, GEMM_SMEM);

    detect_kernel<<<1, 256>>>((const int*)ei, 512);
    deg_init<<<(N + 255) / 256, 256>>>(N);
    deg_count<<<(E + 255) / 256, 256>>>(ei, E);
    dinv_kernel<<<(N + 255) / 256, 256>>>(N);

    dim3 ggrid((N + 127) / 128, 2);
    gemm_mma_kernel<<<ggrid, 256, GEMM_SMEM>>>(x, W, Wl, out, N);

    long long sw = (long long)E * 32;
    scatter_kernel<<<(unsigned)((sw + 255) / 256), 256>>>(ei, out, E);

    long long lw = (long long)N * 32;
    ln_kernel<<<(unsigned)((lw + 255) / 256), 256>>>(out, b, bl, gamma, beta, N);
}

// round 5
// speedup vs baseline: 1.8366x; 1.4675x over previous
#include <cuda_runtime.h>
#include <cuda_bf16.h>
#include <cstdint>

#define D 128
#define NMAX 100000
#define EMAX 1600000
#define SCAN_B 1024

// -------- scratch (static device allocations; no cudaMalloc allowed) --------
__device__ float g_xw[(size_t)NMAX * D];   // x @ W   (51.2 MB)
__device__ float g_dinv[NMAX];
__device__ int   g_deg[NMAX];
__device__ int   g_row[NMAX];              // CSR row offsets (exclusive scan)
__device__ int   g_cur[NMAX];              // fill cursors
__device__ int   g_csr[EMAX];              // edge sources bucketed by dst
__device__ int   g_bsum[(NMAX + SCAN_B - 1) / SCAN_B];
__device__ int   g_is64;

// ---------------------------------------------------------------------------
// dtype detection: edge_index may be int64 or int32.
// ---------------------------------------------------------------------------
__global__ void detect_kernel(const int* ei32, int nsamp) {
    __shared__ int s_nonzero;
    if (threadIdx.x == 0) s_nonzero = 0;
    __syncthreads();
    int bad = 0;
    for (int i = threadIdx.x; i < nsamp; i += blockDim.x)
        if (ei32[2 * i + 1] != 0) bad = 1;
    if (bad) atomicOr(&s_nonzero, 1);
    __syncthreads();
    if (threadIdx.x == 0) g_is64 = s_nonzero ? 0 : 1;
}

__global__ void deg_init(int n) {
    int i = blockIdx.x * blockDim.x + threadIdx.x;
    if (i < n) g_deg[i] = 1;   // self loop
}

__global__ void deg_count(const void* ei, int E) {
    int e = blockIdx.x * blockDim.x + threadIdx.x;
    if (e >= E) return;
    int d;
    if (g_is64) d = (int)((const long long*)ei)[(size_t)E + e];
    else        d = ((const int*)ei)[(size_t)E + e];
    atomicAdd(&g_deg[d], 1);
}

__global__ void dinv_kernel(int n) {
    int i = blockIdx.x * blockDim.x + threadIdx.x;
    if (i < n) g_dinv[i] = rsqrtf((float)g_deg[i]);
}

// ---------------------------------------------------------------------------
// Exclusive scan of edge counts (deg-1) -> g_row, in 3 passes.
// ---------------------------------------------------------------------------
__global__ __launch_bounds__(SCAN_B) void scan1_kernel(int n) {
    __shared__ int sh[SCAN_B];
    int tid = threadIdx.x;
    int i = blockIdx.x * SCAN_B + tid;
    int v = (i < n) ? (g_deg[i] - 1) : 0;
    sh[tid] = v;
    __syncthreads();
    #pragma unroll
    for (int off = 1; off < SCAN_B; off <<= 1) {
        int t = (tid >= off) ? sh[tid - off] : 0;
        __syncthreads();
        sh[tid] += t;
        __syncthreads();
    }
    if (i < n) g_row[i] = sh[tid] - v;          // exclusive
    if (tid == SCAN_B - 1) g_bsum[blockIdx.x] = sh[tid];
}

__global__ __launch_bounds__(SCAN_B) void scan2_kernel(int nb) {
    __shared__ int sh[SCAN_B];
    int tid = threadIdx.x;
    int v = (tid < nb) ? g_bsum[tid] : 0;
    sh[tid] = v;
    __syncthreads();
    #pragma unroll
    for (int off = 1; off < SCAN_B; off <<= 1) {
        int t = (tid >= off) ? sh[tid - off] : 0;
        __syncthreads();
        sh[tid] += t;
        __syncthreads();
    }
    if (tid < nb) g_bsum[tid] = sh[tid] - v;    // exclusive
}

__global__ __launch_bounds__(SCAN_B) void scan3_kernel(int n) {
    int i = blockIdx.x * SCAN_B + threadIdx.x;
    if (i < n) {
        int r = g_row[i] + g_bsum[blockIdx.x];
        g_row[i] = r;
        g_cur[i] = r;
    }
}

// ---------------------------------------------------------------------------
// CSR fill: bucket edge sources by destination.
// ---------------------------------------------------------------------------
__global__ __launch_bounds__(256) void fill_kernel(const void* ei, int E) {
    int e = blockIdx.x * blockDim.x + threadIdx.x;
    if (e >= E) return;
    int s, d;
    if (g_is64) {
        const long long* p = (const long long*)ei;
        s = (int)p[e];
        d = (int)p[(size_t)E + e];
    } else {
        const int* p = (const int*)ei;
        s = p[e];
        d = p[(size_t)E + e];
    }
    int pos = atomicAdd(&g_cur[d], 1);
    g_csr[pos] = s;
}

// ===========================================================================
// GEMM via mma.sync.m16n8k16 bf16 (fp32 accum), hi/lo split for fp32 accuracy.
// Unchanged from R4 (proven).
// ===========================================================================

#define SSTR 136
#define TILE_B (128 * SSTR * 2)
#define OFF_AHI 0
#define OFF_ALO (TILE_B)
#define OFF_BHI (2 * TILE_B)
#define OFF_BLO (3 * TILE_B)
#define GEMM_SMEM (4 * TILE_B)

__device__ __forceinline__ uint32_t smem_u32(const void* p) {
    uint32_t a;
    asm("{ .reg .u64 t; cvta.to.shared.u64 t, %1; cvt.u32.u64 %0, t; }"
        : "=r"(a) : "l"(p));
    return a;
}

__device__ __forceinline__ void ldsm_x4(uint32_t& r0, uint32_t& r1,
                                        uint32_t& r2, uint32_t& r3, uint32_t addr) {
    asm volatile("ldmatrix.sync.aligned.m8n8.x4.shared.b16 {%0,%1,%2,%3}, [%4];"
                 : "=r"(r0), "=r"(r1), "=r"(r2), "=r"(r3) : "r"(addr));
}

__device__ __forceinline__ void mma16816(float* c, const uint32_t* a,
                                         const uint32_t* b) {
    asm volatile(
        "mma.sync.aligned.m16n8k16.row.col.f32.bf16.bf16.f32 "
        "{%0,%1,%2,%3}, {%4,%5,%6,%7}, {%8,%9}, {%0,%1,%2,%3};"
        : "+f"(c[0]), "+f"(c[1]), "+f"(c[2]), "+f"(c[3])
        : "r"(a[0]), "r"(a[1]), "r"(a[2]), "r"(a[3]), "r"(b[0]), "r"(b[1]));
}

__global__ __launch_bounds__(256, 1) void gemm_mma_kernel(
    const float* __restrict__ x,
    const float* __restrict__ W,
    const float* __restrict__ Wl,
    float* __restrict__ outh, int M)
{
    extern __shared__ char smem[];
    const uint32_t sb = smem_u32(smem);
    const int tid  = threadIdx.x;
    const int wid  = tid >> 5;
    const int lane = tid & 31;
    const int row0 = blockIdx.x * 128;

    const float* B = (blockIdx.y == 0) ? W : Wl;
    float* Cout    = (blockIdx.y == 0) ? g_xw : outh;

    {
        const int r  = tid >> 1;
        const int hf = tid & 1;
        const int grow = row0 + r;
        const bool ok = grow < M;
        const float* xr = x + (size_t)(ok ? grow : 0) * D + hf * 64;
        char* pHi = smem + OFF_AHI;
        char* pLo = smem + OFF_ALO;
        const uint32_t rb = (uint32_t)(r * SSTR + hf * 64) * 2;
        #pragma unroll
        for (int c4 = 0; c4 < 16; c4++) {
            float4 v = ok ? *(const float4*)&xr[c4 * 4]
                          : make_float4(0.f, 0.f, 0.f, 0.f);
            float f[4] = { v.x, v.y, v.z, v.w };
            __nv_bfloat16 h[4], l[4];
            #pragma unroll
            for (int j = 0; j < 4; j++) {
                h[j] = __float2bfloat16(f[j]);
                l[j] = __float2bfloat16(f[j] - __bfloat162float(h[j]));
            }
            *(__nv_bfloat162*)(pHi + rb + c4 * 8)     = __nv_bfloat162(h[0], h[1]);
            *(__nv_bfloat162*)(pHi + rb + c4 * 8 + 4) = __nv_bfloat162(h[2], h[3]);
            *(__nv_bfloat162*)(pLo + rb + c4 * 8)     = __nv_bfloat162(l[0], l[1]);
            *(__nv_bfloat162*)(pLo + rb + c4 * 8 + 4) = __nv_bfloat162(l[2], l[3]);
        }
    }

    {
        const int n  = tid >> 1;
        const int kh = tid & 1;
        const float* bp = B + n + (size_t)kh * 64 * D;
        char* pHi = smem + OFF_BHI;
        char* pLo = smem + OFF_BLO;
        #pragma unroll 4
        for (int kk = 0; kk < 64; kk++) {
            float f = bp[(size_t)kk * D];
            __nv_bfloat16 h = __float2bfloat16(f);
            __nv_bfloat16 l = __float2bfloat16(f - __bfloat162float(h));
            uint32_t off = (uint32_t)(n * SSTR + kh * 64 + kk) * 2;
            *(__nv_bfloat16*)(pHi + off) = h;
            *(__nv_bfloat16*)(pLo + off) = l;
        }
    }
    __syncthreads();

    const int mi = wid & 3;
    const int ni = wid >> 2;

    float c[2][8][4];
    #pragma unroll
    for (int mt = 0; mt < 2; mt++)
        #pragma unroll
        for (int nt = 0; nt < 8; nt++)
            #pragma unroll
            for (int q = 0; q < 4; q++) c[mt][nt][q] = 0.f;

    const int lmat = lane >> 3;
    const int lr   = lane & 7;
    const int rowc = ((lmat & 1) << 3) + lr;
    const int colc = (lmat >> 1) << 3;

    #pragma unroll
    for (int p = 0; p < 3; p++) {
        const uint32_t abase = sb + ((p < 2) ? OFF_AHI : OFF_ALO);
        const uint32_t bbase = sb + ((p == 1) ? OFF_BLO : OFF_BHI);
        const uint32_t a_rc = (uint32_t)((mi * 32 + rowc) * SSTR + colc) * 2;
        const uint32_t b_rc = (uint32_t)((ni * 64 + rowc) * SSTR + colc) * 2;

        #pragma unroll
        for (int k0 = 0; k0 < 8; k0++) {
            const uint32_t kb = (uint32_t)(k0 * 16) * 2;
            uint32_t afr[2][4];
            #pragma unroll
            for (int mt = 0; mt < 2; mt++)
                ldsm_x4(afr[mt][0], afr[mt][1], afr[mt][2], afr[mt][3],
                        abase + a_rc + kb + (uint32_t)(mt * 16 * SSTR) * 2);
            uint32_t bfr[8][2];
            #pragma unroll
            for (int nb = 0; nb < 4; nb++) {
                uint32_t r0, r1, r2, r3;
                ldsm_x4(r0, r1, r2, r3,
                        bbase + b_rc + kb + (uint32_t)(nb * 16 * SSTR) * 2);
                bfr[nb * 2][0]     = r0;  bfr[nb * 2][1]     = r2;
                bfr[nb * 2 + 1][0] = r1;  bfr[nb * 2 + 1][1] = r3;
            }
            #pragma unroll
            for (int mt = 0; mt < 2; mt++)
                #pragma unroll
                for (int nt = 0; nt < 8; nt++)
                    mma16816(c[mt][nt], afr[mt], bfr[nt]);
        }
    }

    const int g   = lane >> 2;
    const int tig = lane & 3;
    #pragma unroll
    for (int mt = 0; mt < 2; mt++) {
        #pragma unroll
        for (int nt = 0; nt < 8; nt++) {
            const int col  = ni * 64 + nt * 8 + tig * 2;
            const int row  = row0 + mi * 32 + mt * 16 + g;
            if (row < M)
                *(float2*)&Cout[(size_t)row * D + col] =
                    make_float2(c[mt][nt][0], c[mt][nt][1]);
            if (row + 8 < M)
                *(float2*)&Cout[(size_t)(row + 8) * D + col] =
                    make_float2(c[mt][nt][2], c[mt][nt][3]);
        }
    }
}

// ---------------------------------------------------------------------------
// Fused gather + self-loop + residual + LayerNorm. One warp per dst node.
//   agg = sum_{s in csr[row]} xw[s]*dinv[s];
//   h   = agg*dinv[r] + xw[r]*dinv[r]^2 + residual(out) + b + bl;  out = LN(h)
// ---------------------------------------------------------------------------
__global__ __launch_bounds__(256) void gather_ln_kernel(
    float* __restrict__ out,
    const float* __restrict__ b,  const float* __restrict__ bl,
    const float* __restrict__ gamma, const float* __restrict__ beta, int n)
{
    int gtid = blockIdx.x * blockDim.x + threadIdx.x;
    int r    = gtid >> 5;
    int lane = gtid & 31;
    if (r >= n) return;

    const int start = g_row[r];
    const int cnt   = g_deg[r] - 1;
    const float di  = g_dinv[r];
    const int j = lane * 4;

    float ax = 0.f, ay = 0.f, az = 0.f, aw = 0.f;
    for (int base = 0; base < cnt; base += 32) {
        int m = cnt - base;
        int lim = m < 32 ? m : 32;
        int   idx = 0;
        float dsv = 0.f;
        if (lane < lim) {
            idx = g_csr[start + base + lane];
            dsv = g_dinv[idx];
        }
        for (int k = 0; k < lim; k++) {
            int   s = __shfl_sync(0xFFFFFFFFu, idx, k);
            float c = __shfl_sync(0xFFFFFFFFu, dsv, k);
            float4 v = *(const float4*)&g_xw[(size_t)s * D + j];
            ax += v.x * c; ay += v.y * c; az += v.z * c; aw += v.w * c;
        }
    }

    const float sd = di * di;
    float4 xw  = *(const float4*)&g_xw[(size_t)r * D + j];
    float4 res = *(float4*)&out[(size_t)r * D + j];
    float4 b4  = *(const float4*)&b[j];
    float4 l4  = *(const float4*)&bl[j];
    float hx = ax * di + xw.x * sd + res.x + b4.x + l4.x;
    float hy = ay * di + xw.y * sd + res.y + b4.y + l4.y;
    float hz = az * di + xw.z * sd + res.z + b4.z + l4.z;
    float hw = aw * di + xw.w * sd + res.w + b4.w + l4.w;

    float s = hx + hy + hz + hw;
    #pragma unroll
    for (int o = 16; o > 0; o >>= 1) s += __shfl_xor_sync(0xFFFFFFFFu, s, o);
    float mu = s * (1.f / 128.f);

    float dx = hx - mu, dy = hy - mu, dz = hz - mu, dw = hw - mu;
    float sq = dx * dx + dy * dy + dz * dz + dw * dw;
    #pragma unroll
    for (int o = 16; o > 0; o >>= 1) sq += __shfl_xor_sync(0xFFFFFFFFu, sq, o);
    float rstd = rsqrtf(sq * (1.f / 128.f) + 1e-5f);

    float4 g4 = *(const float4*)&gamma[j];
    float4 e4 = *(const float4*)&beta[j];
    float4 o4;
    o4.x = dx * rstd * g4.x + e4.x;
    o4.y = dy * rstd * g4.y + e4.y;
    o4.z = dz * rstd * g4.z + e4.z;
    o4.w = dw * rstd * g4.w + e4.w;
    *(float4*)&out[(size_t)r * D + j] = o4;
}

// ---------------------------------------------------------------------------
extern "C" void kernel_launch(void* const* d_in, const int* in_sizes, int n_in,
                              void* d_out, int out_size)
{
    const float* x     = (const float*)d_in[0];
    const void*  ei    = d_in[1];
    const float* W     = (const float*)d_in[2];
    const float* b     = (const float*)d_in[3];
    const float* Wl    = (const float*)d_in[4];
    const float* bl    = (const float*)d_in[5];
    const float* gamma = (const float*)d_in[6];
    const float* beta  = (const float*)d_in[7];
    float* out = (float*)d_out;

    int N = in_sizes[0] / D;
    int E = in_sizes[1] / 2;
    int nb = (N + SCAN_B - 1) / SCAN_B;

    cudaFuncSetAttribute(gemm_mma_kernel,
                         cudaFuncAttributeMaxDynamicSharedMemorySize, GEMM_SMEM);

    detect_kernel<<<1, 256>>>((const int*)ei, 512);
    deg_init<<<(N + 255) / 256, 256>>>(N);
    deg_count<<<(E + 255) / 256, 256>>>(ei, E);
    dinv_kernel<<<(N + 255) / 256, 256>>>(N);

    scan1_kernel<<<nb, SCAN_B>>>(N);
    scan2_kernel<<<1, SCAN_B>>>(nb);
    scan3_kernel<<<nb, SCAN_B>>>(N);
    fill_kernel<<<(E + 255) / 256, 256>>>(ei, E);

    dim3 ggrid((N + 127) / 128, 2);
    gemm_mma_kernel<<<ggrid, 256, GEMM_SMEM>>>(x, W, Wl, out, N);

    long long lw = (long long)N * 32;
    gather_ln_kernel<<<(unsigned)((lw + 255) / 256), 256>>>(out, b, bl, gamma, beta, N);
}